// round 3
// baseline (speedup 1.0000x reference)
#include <cuda_runtime.h>

// x:   [B, N, 128] f32  -> [B*N, 32] float4 ; R: [B*N] float4 (r00,r01,r10,r11)
// y0 = r00*x0 + r01*x1 ; y1 = r10*x0 + r11*x1 per consecutive pair.
//
// Coalesced + MLP: each block owns UNROLL*blockDim consecutive float4s;
// thread t handles t, t+256, t+512, t+768 within that chunk — every load
// instruction is a perfectly coalesced 512B/warp access, and the 4 loads
// are independent (front-batched by ptxas for MLP).

#define THREADS 256
#define UNROLL 4

__device__ __forceinline__ float4 rot4(float4 r, float4 v) {
    float4 o;
    o.x = fmaf(r.x, v.x, r.y * v.y);
    o.y = fmaf(r.z, v.x, r.w * v.y);
    o.z = fmaf(r.x, v.z, r.y * v.w);
    o.w = fmaf(r.z, v.z, r.w * v.w);
    return o;
}

__global__ __launch_bounds__(THREADS) void rot2_kernel(
    const float4* __restrict__ x,
    const float4* __restrict__ R,
    float4* __restrict__ out,
    int n4)
{
    int base = blockIdx.x * (THREADS * UNROLL) + threadIdx.x;

    int   idx[UNROLL];
    float4 v[UNROLL];
    float4 r[UNROLL];

    // Front-batched independent loads (grid is sized so all are in-bounds;
    // n4 = 8,388,608 is divisible by 1024, but keep a guard for safety).
    if (base + (UNROLL - 1) * THREADS < n4) {
#pragma unroll
        for (int k = 0; k < UNROLL; k++) {
            idx[k] = base + k * THREADS;
            v[k] = x[idx[k]];
        }
#pragma unroll
        for (int k = 0; k < UNROLL; k++)
            r[k] = __ldg(&R[idx[k] >> 5]);   // 32 float4 per point
#pragma unroll
        for (int k = 0; k < UNROLL; k++)
            out[idx[k]] = rot4(r[k], v[k]);
    } else {
#pragma unroll
        for (int k = 0; k < UNROLL; k++) {
            int i = base + k * THREADS;
            if (i < n4) out[i] = rot4(__ldg(&R[i >> 5]), x[i]);
        }
    }
}

extern "C" void kernel_launch(void* const* d_in, const int* in_sizes, int n_in,
                              void* d_out, int out_size)
{
    const float4* x = (const float4*)d_in[0];
    const float4* R = (const float4*)d_in[1];
    float4* out = (float4*)d_out;

    int n4 = out_size / 4;                          // 8,388,608
    int per_block = THREADS * UNROLL;               // 1024
    int blocks = (n4 + per_block - 1) / per_block;  // 8192
    rot2_kernel<<<blocks, THREADS>>>(x, R, out, n4);
}

// round 4
// speedup vs baseline: 1.1071x; 1.1071x over previous
#include <cuda_runtime.h>

// x:   [B, N, 128] f32  -> viewed as [B*N, 32] float4
// R:   [B, N, 2, 2] f32 -> viewed as [B*N] float4 (r00, r01, r10, r11)
// y0 = r00*x0 + r01*x1 ; y1 = r10*x0 + r11*x1 for each consecutive pair.
//
// One float4 per thread (perfectly coalesced, max warp count for latency
// hiding). Each aligned warp covers exactly one point, so the R load is a
// single broadcast line per warp. x/out use evict-first streaming policy;
// R keeps the default cached path.

__global__ __launch_bounds__(256) void rot2_kernel(
    const float4* __restrict__ x,
    const float4* __restrict__ R,
    float4* __restrict__ out,
    int n4)
{
    int i = blockIdx.x * blockDim.x + threadIdx.x;
    if (i >= n4) return;

    float4 r = __ldg(&R[i >> 5]);       // 32 float4 per point; warp broadcast
    float4 v = __ldcs(&x[i]);           // streaming read, evict-first

    float4 o;
    o.x = fmaf(r.x, v.x, r.y * v.y);
    o.y = fmaf(r.z, v.x, r.w * v.y);
    o.z = fmaf(r.x, v.z, r.y * v.w);
    o.w = fmaf(r.z, v.z, r.w * v.w);
    __stcs(&out[i], o);                 // streaming write, evict-first
}

extern "C" void kernel_launch(void* const* d_in, const int* in_sizes, int n_in,
                              void* d_out, int out_size)
{
    const float4* x = (const float4*)d_in[0];
    const float4* R = (const float4*)d_in[1];
    float4* out = (float4*)d_out;

    int n4 = out_size / 4;              // 8,388,608 float4
    int threads = 256;
    int blocks = (n4 + threads - 1) / threads;
    rot2_kernel<<<blocks, threads>>>(x, R, out, n4);
}